// round 8
// baseline (speedup 1.0000x reference)
#include <cuda_runtime.h>
#include <cuda_bf16.h>
#include <cuda_fp8.h>
#include <float.h>
#include <stdint.h>

#define B_   32
#define D_   512
#define HW_  1024
#define N_   32768
#define K_   4096

#define TOK_PER_CTA 128
#define NTILE       128                  // codes per tile
#define NUM_TILES   (K_ / NTILE)         // 32
#define GCHUNKS     (NUM_TILES * 4)      // 128 chunks of 128 fp8 in k
#define CAP         64
#define MARGIN_F    24.0f

// ---- smem layout (bytes) ----
#define AP8       528                    // A row pitch: 512 + 16
#define BP8       144                    // B row pitch: 128 + 16
#define BBUF_B    (128 * BP8)            // 18432 per buffer
#define SM_A      0                      // 128 * 528 = 67584
#define SM_B      67584                  // 2 * 18432 = 36864
#define SM_ESQ    104448                 // 128 floats
#define SM_SCNT   104960                 // 128 ints
#define SM_WMIN   105472                 // 128 * 2 * float2 = 2048
#define SM_TOTAL  107520

// ---- scratch ----
__device__ uint8_t g_Z8[(size_t)N_ * D_];      // e4m3, token-major
__device__ float   g_Zf[(size_t)N_ * D_];      // fp32, token-major
__device__ uint8_t g_E8[(size_t)K_ * D_];      // e4m3
__device__ float   g_esq[K_];
__device__ float2  g_cand[N_][CAP];
__device__ int     g_ccnt[N_];
__device__ float   g_amin[N_];
__device__ int     g_kidx[N_];
__device__ double  g_loss;

// ================= helpers =================
__device__ __forceinline__ uint32_t smem_u32(const void* p) {
    uint32_t a;
    asm("{ .reg .u64 t; cvta.to.shared.u64 t, %1; cvt.u32.u64 %0, t; }" : "=r"(a) : "l"(p));
    return a;
}
__device__ __forceinline__ void ldsm_x4(uint32_t& r0, uint32_t& r1, uint32_t& r2, uint32_t& r3,
                                        uint32_t addr) {
    asm volatile("ldmatrix.sync.aligned.m8n8.x4.shared.b16 {%0,%1,%2,%3}, [%4];"
                 : "=r"(r0), "=r"(r1), "=r"(r2), "=r"(r3) : "r"(addr));
}
__device__ __forceinline__ void mma16832f8(float* d, const uint32_t* a, const uint32_t* b) {
    asm volatile("mma.sync.aligned.m16n8k32.row.col.f32.e4m3.e4m3.f32 "
                 "{%0,%1,%2,%3}, {%4,%5,%6,%7}, {%8,%9}, {%0,%1,%2,%3};"
                 : "+f"(d[0]), "+f"(d[1]), "+f"(d[2]), "+f"(d[3])
                 : "r"(a[0]), "r"(a[1]), "r"(a[2]), "r"(a[3]), "r"(b[0]), "r"(b[1]));
}
__device__ __forceinline__ void cp16(uint32_t dst, const void* src) {
    asm volatile("cp.async.ca.shared.global [%0], [%1], 16;" :: "r"(dst), "l"(src));
}
#define CP_COMMIT() asm volatile("cp.async.commit_group;" ::: "memory")
#define CP_WAIT0()  asm volatile("cp.async.wait_group 0;" ::: "memory")

__device__ __forceinline__ uint8_t to_e4m3(float v) {
    return (uint8_t)__nv_cvt_float_to_fp8(v, __NV_SATFINITE, __NV_E4M3);
}

// ============================================================
// K0: X[NCHW] -> Zf fp32 + Z8 e4m3 (token-major)
// ============================================================
__global__ void k_prep_z(const float* __restrict__ X) {
    __shared__ float tile[32][33];
    int b = blockIdx.z, d0 = blockIdx.y * 32, hw0 = blockIdx.x * 32;
    int tx = threadIdx.x, ty = threadIdx.y;       // (32, 8)
#pragma unroll
    for (int i = 0; i < 32; i += 8)
        tile[ty + i][tx] = X[((size_t)b * D_ + d0 + ty + i) * HW_ + hw0 + tx];
    __syncthreads();
#pragma unroll
    for (int i = 0; i < 32; i += 8) {
        size_t idx = (size_t)(b * HW_ + hw0 + ty + i) * D_ + d0 + tx;
        float v = tile[tx][ty + i];
        g_Zf[idx] = v;
        g_Z8[idx] = to_e4m3(v);
    }
}

// ============================================================
// K1: E -> E8 e4m3 + ||e||^2; zero loss
// ============================================================
__global__ void k_prep_e(const float* __restrict__ E) {
    int row = blockIdx.x, t = threadIdx.x;        // 128 threads
    float s = 0.f;
#pragma unroll
    for (int i = t; i < D_; i += 128) {
        float v = E[(size_t)row * D_ + i];
        g_E8[(size_t)row * D_ + i] = to_e4m3(v);
        s += v * v;
    }
#pragma unroll
    for (int o = 16; o > 0; o >>= 1) s += __shfl_down_sync(0xffffffffu, s, o);
    __shared__ float sb[4];
    if ((t & 31) == 0) sb[t >> 5] = s;
    __syncthreads();
    if (t == 0) {
        g_esq[row] = sb[0] + sb[1] + sb[2] + sb[3];
        if (row == 0) g_loss = 0.0;
    }
}

// ============================================================
// K2: fp8 mma.sync GEMM + margin argmin / candidate collection
// ============================================================
__global__ void __launch_bounds__(256, 2) k_gemm() {
    extern __shared__ char smem[];
    uint32_t sbase = smem_u32(smem);
    int tid = threadIdx.x;
    int lane = tid & 31, wid = tid >> 5;
    int wm = wid >> 1, wn = wid & 1;
    int tok0 = blockIdx.x * TOK_PER_CTA;

    float*  esq_s = (float*)(smem + SM_ESQ);
    int*    scnt  = (int*)(smem + SM_SCNT);
    float2* wmin  = (float2*)(smem + SM_WMIN);

    if (tid < 128) scnt[tid] = 0;

    // ---- load A resident: 128 tokens x 512 fp8, padded rows ----
    {
        const uint4* src = (const uint4*)(g_Z8 + (size_t)tok0 * D_);
        for (int i = tid; i < 128 * 32; i += 256) {
            int r = i >> 5, c = i & 31;
            uint4 v = src[(size_t)r * 32 + c];
            *(uint4*)(smem + SM_A + r * AP8 + c * 16) = v;
        }
    }

    // per-lane ldmatrix base addresses
    uint32_t aAddr[2];
#pragma unroll
    for (int mf = 0; mf < 2; mf++) {
        int rowA = wm * 32 + mf * 16 + (lane & 15);
        aAddr[mf] = sbase + SM_A + rowA * AP8 + (lane >> 4) * 16;
    }
    uint32_t bAddr[4];
#pragma unroll
    for (int n16 = 0; n16 < 4; n16++) {
        int rowB = wn * 64 + n16 * 16 + (lane & 7) + ((lane >> 4) << 3);
        bAddr[n16] = sbase + SM_B + rowB * BP8 + ((lane >> 3) & 1) * 16;
    }

    // prefetch chunk 0 of tile 0  (128 codes x 128 fp8)
    {
        int row = tid >> 1, half = tid & 1;
        const uint8_t* src = g_E8 + (size_t)row * D_ + half * 64;
        uint32_t dst = sbase + SM_B + row * BP8 + half * 64;
#pragma unroll
        for (int i = 0; i < 4; i++) cp16(dst + i * 16, src + i * 16);
        CP_COMMIT();
    }

    float acc[2][8][4];
#pragma unroll
    for (int mf = 0; mf < 2; mf++)
#pragma unroll
        for (int nf = 0; nf < 8; nf++)
#pragma unroll
            for (int v = 0; v < 4; v++) acc[mf][nf][v] = 0.f;

    float runmin[4]; int runk[4];
#pragma unroll
    for (int s = 0; s < 4; s++) { runmin[s] = FLT_MAX; runk[s] = 0; }

    for (int g = 0; g < GCHUNKS; g++) {
        CP_WAIT0();
        __syncthreads();

        if ((g & 3) == 0 && tid < 128)
            esq_s[tid] = g_esq[(g >> 2) * NTILE + tid];

        // prefetch next chunk into the other buffer
        if (g + 1 < GCHUNKS) {
            int gn = g + 1;
            int n0n = (gn >> 2) * NTILE;
            int row = tid >> 1, half = tid & 1;
            const uint8_t* src = g_E8 + (size_t)(n0n + row) * D_ + (gn & 3) * 128 + half * 64;
            uint32_t dst = sbase + SM_B + (gn & 1) * BBUF_B + row * BP8 + half * 64;
#pragma unroll
            for (int i = 0; i < 4; i++) cp16(dst + i * 16, src + i * 16);
            CP_COMMIT();
        }

        // ---- compute: 4 k-steps of 32 on buffer g&1 ----
        uint32_t kbA = (uint32_t)((g & 3) * 128);
        uint32_t bb  = (uint32_t)((g & 1) * BBUF_B);
#pragma unroll
        for (int ks = 0; ks < 4; ks++) {
            uint32_t a0[4], a1[4];
            ldsm_x4(a0[0], a0[1], a0[2], a0[3], aAddr[0] + kbA + ks * 32);
            ldsm_x4(a1[0], a1[1], a1[2], a1[3], aAddr[1] + kbA + ks * 32);
            uint32_t bfr[8][2];
#pragma unroll
            for (int n16 = 0; n16 < 4; n16++)
                ldsm_x4(bfr[2 * n16][0], bfr[2 * n16][1],
                        bfr[2 * n16 + 1][0], bfr[2 * n16 + 1][1],
                        bAddr[n16] + bb + ks * 32);
#pragma unroll
            for (int nf = 0; nf < 8; nf++) {
                mma16832f8(acc[0][nf], a0, bfr[nf]);
                mma16832f8(acc[1][nf], a1, bfr[nf]);
            }
        }

        // ---- tile epilogue after last chunk of tile ----
        if ((g & 3) == 3) {
            int n0 = (g >> 2) * NTILE;
            // pass 1: per-lane slot minima (slot = mf*2 + rowhalf)
            float sm[4]; int sk[4];
#pragma unroll
            for (int s = 0; s < 4; s++) { sm[s] = FLT_MAX; sk[s] = 0; }
#pragma unroll
            for (int mf = 0; mf < 2; mf++)
#pragma unroll
                for (int nf = 0; nf < 8; nf++)
#pragma unroll
                    for (int v = 0; v < 4; v++) {
                        float e = esq_s[wn * 64 + nf * 8 + (lane & 3) * 2 + (v & 1)];
                        float dist = fmaf(-2.f, acc[mf][nf][v], e);
                        int slot = mf * 2 + (v >> 1);
                        int k = n0 + wn * 64 + nf * 8 + (lane & 3) * 2 + (v & 1);
                        if (dist < sm[slot]) { sm[slot] = dist; sk[slot] = k; }
                    }
            // quad reduce (lanes sharing a row)
#pragma unroll
            for (int off = 1; off <= 2; off <<= 1) {
#pragma unroll
                for (int s = 0; s < 4; s++) {
                    float od = __shfl_xor_sync(0xffffffffu, sm[s], off);
                    int   ok = __shfl_xor_sync(0xffffffffu, sk[s], off);
                    if (od < sm[s] || (od == sm[s] && ok < sk[s])) { sm[s] = od; sk[s] = ok; }
                }
            }
#pragma unroll
            for (int s = 0; s < 4; s++)
                if (sm[s] < runmin[s]) { runmin[s] = sm[s]; runk[s] = sk[s]; }
            // pass 2: margin appends
#pragma unroll
            for (int mf = 0; mf < 2; mf++)
#pragma unroll
                for (int nf = 0; nf < 8; nf++)
#pragma unroll
                    for (int v = 0; v < 4; v++) {
                        float e = esq_s[wn * 64 + nf * 8 + (lane & 3) * 2 + (v & 1)];
                        float dist = fmaf(-2.f, acc[mf][nf][v], e);
                        int slot = mf * 2 + (v >> 1);
                        if (dist < runmin[slot] + MARGIN_F) {
                            int row = wm * 32 + mf * 16 + (lane >> 2) + (v >> 1) * 8;
                            int k = n0 + wn * 64 + nf * 8 + (lane & 3) * 2 + (v & 1);
                            int s = atomicAdd(&scnt[row], 1);
                            if (s < CAP)
                                g_cand[tok0 + row][s] = make_float2(dist, __int_as_float(k));
                        }
                        acc[mf][nf][v] = 0.f;   // reset for next tile
                    }
        }
        __syncthreads();
    }

    // ---- final: per-warp row minima -> smem -> global ----
    if ((lane & 3) == 0) {
#pragma unroll
        for (int s = 0; s < 4; s++) {
            int mf = s >> 1, rh = s & 1;
            int row = wm * 32 + mf * 16 + (lane >> 2) + rh * 8;
            wmin[row * 2 + wn] = make_float2(runmin[s], __int_as_float(runk[s]));
        }
    }
    __syncthreads();
    if (tid < 128) {
        float2 a = wmin[tid * 2 + 0], b = wmin[tid * 2 + 1];
        g_amin[tok0 + tid] = fminf(a.x, b.x);
        g_ccnt[tok0 + tid] = scnt[tid];
    }
}

// ============================================================
// K3: exact fp32 rescore of candidates -> g_kidx
// ============================================================
__global__ void __launch_bounds__(128) k_rescore(const float* __restrict__ E) {
    int tok = blockIdx.x * 4 + (threadIdx.x >> 5);
    int lid = threadIdx.x & 31;
    float z[16];
#pragma unroll
    for (int j = 0; j < 16; j++) z[j] = g_Zf[(size_t)tok * D_ + j * 32 + lid];

    int cnt = g_ccnt[tok];
    float amin = g_amin[tok];
    float best = FLT_MAX;
    int bi = 0x7fffffff;

    if (cnt <= CAP) {
        for (int c = 0; c < cnt; c++) {
            float2 cd = g_cand[tok][c];
            if (cd.x > amin + MARGIN_F) continue;      // warp-uniform
            int k = __float_as_int(cd.y);
            float p = 0.f;
            const float* er = E + (size_t)k * D_;
#pragma unroll
            for (int j = 0; j < 16; j++) p += z[j] * er[j * 32 + lid];
#pragma unroll
            for (int o = 16; o > 0; o >>= 1) p += __shfl_down_sync(0xffffffffu, p, o);
            if (lid == 0) {
                float dist = g_esq[k] - 2.0f * p;
                if (dist < best || (dist == best && k < bi)) { best = dist; bi = k; }
            }
        }
    } else {
        // overflow safety net: exact scan of all codes (rare)
        for (int k = 0; k < K_; k++) {
            float p = 0.f;
            const float* er = E + (size_t)k * D_;
#pragma unroll
            for (int j = 0; j < 16; j++) p += z[j] * er[j * 32 + lid];
#pragma unroll
            for (int o = 16; o > 0; o >>= 1) p += __shfl_down_sync(0xffffffffu, p, o);
            if (lid == 0) {
                float dist = g_esq[k] - 2.0f * p;
                if (dist < best) { best = dist; bi = k; }
            }
        }
    }
    if (lid == 0) g_kidx[tok] = bi;
}

// ============================================================
// K4: gather + NCHW output + loss partial
// ============================================================
__global__ void __launch_bounds__(256) k_output(const float* __restrict__ X,
                                                const float* __restrict__ E,
                                                float* __restrict__ out) {
    __shared__ float S[64][65];
    __shared__ int karr[64];
    __shared__ float rbuf[8];
    int t = threadIdx.x;
    int base = blockIdx.x * 64;
    int b = base >> 10, hw0 = base & 1023;
    if (t < 64) karr[t] = g_kidx[base + t];
    __syncthreads();

    float lsum = 0.f;
    size_t blk_base = (size_t)b * D_ * HW_ + hw0;
    for (int dc = 0; dc < D_; dc += 64) {
#pragma unroll
        for (int i = 0; i < 4; i++) {
            int m = (t >> 4) + i * 16;
            int dl = (t & 15) * 4;
            float4 q = *(const float4*)&E[(size_t)karr[m] * D_ + dc + dl];
            S[m][dl] = q.x; S[m][dl + 1] = q.y; S[m][dl + 2] = q.z; S[m][dl + 3] = q.w;
        }
        __syncthreads();
        int hwl = t & 63;
#pragma unroll
        for (int i = 0; i < 16; i++) {
            int dl = (t >> 6) + i * 4;
            size_t addr = blk_base + (size_t)(dc + dl) * HW_ + hwl;
            float z = X[addr];
            float q = S[hwl][dl];
            float df = z - q;
            lsum += df * df;
            out[addr] = q;
        }
        __syncthreads();
    }
#pragma unroll
    for (int o = 16; o > 0; o >>= 1) lsum += __shfl_down_sync(0xffffffffu, lsum, o);
    if ((t & 31) == 0) rbuf[t >> 5] = lsum;
    __syncthreads();
    if (t == 0) {
        float s = 0.f;
#pragma unroll
        for (int w = 0; w < 8; w++) s += rbuf[w];
        atomicAdd(&g_loss, (double)s);
    }
}

__global__ void k_finalize(float* __restrict__ out, int out_size) {
    if (out_size > N_ * D_)
        out[N_ * D_] = (float)(1.25 * g_loss / ((double)N_ * (double)D_));
}

// ============================================================
extern "C" void kernel_launch(void* const* d_in, const int* in_sizes, int n_in,
                              void* d_out, int out_size) {
    const float* X = (const float*)d_in[0];
    const float* E = (const float*)d_in[1];
    if (n_in >= 2 && in_sizes[0] == K_ * D_ && in_sizes[1] == N_ * D_) {
        const float* tmp = X; X = E; E = tmp;
    }
    float* out = (float*)d_out;

    static int smem_set = 0;
    if (!smem_set) {
        cudaFuncSetAttribute(k_gemm, cudaFuncAttributeMaxDynamicSharedMemorySize, SM_TOTAL);
        smem_set = 1;
    }

    k_prep_z<<<dim3(HW_ / 32, D_ / 32, B_), dim3(32, 8)>>>(X);
    k_prep_e<<<K_, 128>>>(E);
    k_gemm<<<N_ / TOK_PER_CTA, 256, SM_TOTAL>>>();
    k_rescore<<<N_ / 4, 128>>>(E);
    k_output<<<N_ / 64, 256>>>(X, E, out);
    k_finalize<<<1, 1>>>(out, out_size);
}

// round 11
// speedup vs baseline: 3.7712x; 3.7712x over previous
#include <cuda_runtime.h>
#include <cuda_bf16.h>
#include <float.h>
#include <stdint.h>

#define B_   32
#define D_   512
#define HW_  1024
#define N_   32768
#define K_   4096

#define TOK_PER_CTA 128
#define NTILE       128                  // codes per tile
#define NUM_TILES   (K_ / NTILE)         // 32
#define GCHUNKS     (NUM_TILES * 4)      // 128 k-chunks of 128 halves
#define CAP         64
#define MARGIN_F    1.5f

// ---- smem layout (bytes) ----
#define AP_B      1040                   // A row pitch: (512+8)*2
#define BP_B      272                    // B row pitch: (128+8)*2
#define BBUF_B    (128 * BP_B)           // 34816 per buffer
#define SM_A      0                      // 128 * 1040 = 133120
#define SM_B      133120                 // 2 * 34816 = 69632
#define SM_ESQ    202752                 // 128 floats
#define SM_SCNT   203264                 // 128 ints
#define SM_WMIN   203776                 // 128 * 4 * float2 = 4096
#define SM_TOTAL  207872

// ---- scratch ----
__device__ __nv_bfloat16 g_Zh[(size_t)N_ * D_];
__device__ float         g_Zf[(size_t)N_ * D_];
__device__ __nv_bfloat16 g_Eh[(size_t)K_ * D_];
__device__ float         g_esq[K_];
__device__ float2        g_cand[N_][CAP];
__device__ int           g_ccnt[N_];
__device__ float         g_amin[N_];
__device__ int           g_kidx[N_];
__device__ double        g_loss;

// ================= helpers =================
__device__ __forceinline__ uint32_t smem_u32(const void* p) {
    uint32_t a;
    asm("{ .reg .u64 t; cvta.to.shared.u64 t, %1; cvt.u32.u64 %0, t; }" : "=r"(a) : "l"(p));
    return a;
}
__device__ __forceinline__ void ldsm_x4(uint32_t& r0, uint32_t& r1, uint32_t& r2, uint32_t& r3,
                                        uint32_t addr) {
    asm volatile("ldmatrix.sync.aligned.m8n8.x4.shared.b16 {%0,%1,%2,%3}, [%4];"
                 : "=r"(r0), "=r"(r1), "=r"(r2), "=r"(r3) : "r"(addr));
}
__device__ __forceinline__ void mma16816(float* d, const uint32_t* a, const uint32_t* b) {
    asm volatile("mma.sync.aligned.m16n8k16.row.col.f32.bf16.bf16.f32 "
                 "{%0,%1,%2,%3}, {%4,%5,%6,%7}, {%8,%9}, {%0,%1,%2,%3};"
                 : "+f"(d[0]), "+f"(d[1]), "+f"(d[2]), "+f"(d[3])
                 : "r"(a[0]), "r"(a[1]), "r"(a[2]), "r"(a[3]), "r"(b[0]), "r"(b[1]));
}
__device__ __forceinline__ void cp16(uint32_t dst, const void* src) {
    asm volatile("cp.async.ca.shared.global [%0], [%1], 16;" :: "r"(dst), "l"(src));
}
#define CP_COMMIT() asm volatile("cp.async.commit_group;" ::: "memory")
#define CP_WAIT0()  asm volatile("cp.async.wait_group 0;" ::: "memory")

// ============================================================
// K0: X[NCHW] -> Zf fp32 + Zh bf16 (token-major)
// ============================================================
__global__ void k_prep_z(const float* __restrict__ X) {
    __shared__ float tile[32][33];
    int b = blockIdx.z, d0 = blockIdx.y * 32, hw0 = blockIdx.x * 32;
    int tx = threadIdx.x, ty = threadIdx.y;       // (32, 8)
#pragma unroll
    for (int i = 0; i < 32; i += 8)
        tile[ty + i][tx] = X[((size_t)b * D_ + d0 + ty + i) * HW_ + hw0 + tx];
    __syncthreads();
#pragma unroll
    for (int i = 0; i < 32; i += 8) {
        size_t idx = (size_t)(b * HW_ + hw0 + ty + i) * D_ + d0 + tx;
        float v = tile[tx][ty + i];
        g_Zf[idx] = v;
        g_Zh[idx] = __float2bfloat16(v);
    }
}

// ============================================================
// K1: E -> Eh bf16 + ||e||^2; zero loss
// ============================================================
__global__ void k_prep_e(const float* __restrict__ E) {
    int row = blockIdx.x, t = threadIdx.x;        // 128 threads
    float s = 0.f;
#pragma unroll
    for (int i = t; i < D_; i += 128) {
        float v = E[(size_t)row * D_ + i];
        g_Eh[(size_t)row * D_ + i] = __float2bfloat16(v);
        s += v * v;
    }
#pragma unroll
    for (int o = 16; o > 0; o >>= 1) s += __shfl_down_sync(0xffffffffu, s, o);
    __shared__ float sb[4];
    if ((t & 31) == 0) sb[t >> 5] = s;
    __syncthreads();
    if (t == 0) {
        g_esq[row] = sb[0] + sb[1] + sb[2] + sb[3];
        if (row == 0) g_loss = 0.0;
    }
}

// ============================================================
// K2: bf16 mma.sync GEMM + margin argmin / candidate collection
//     512 threads, warp grid 4M x 4N, warp tile 32x32
// ============================================================
__global__ void __launch_bounds__(512, 1) k_gemm() {
    extern __shared__ char smem[];
    uint32_t sbase = smem_u32(smem);
    int tid = threadIdx.x;
    int lane = tid & 31, wid = tid >> 5;
    int wm = wid >> 2, wn = wid & 3;
    int tok0 = blockIdx.x * TOK_PER_CTA;

    float*  esq_s = (float*)(smem + SM_ESQ);
    int*    scnt  = (int*)(smem + SM_SCNT);
    float2* wmin  = (float2*)(smem + SM_WMIN);

    if (tid < 128) scnt[tid] = 0;

    // ---- load A resident: 128 tokens x 512 bf16, padded rows ----
    {
        const uint4* src = (const uint4*)(g_Zh + (size_t)tok0 * D_);
        for (int i = tid; i < 128 * 64; i += 512) {
            int r = i >> 6, c = i & 63;
            uint4 v = src[(size_t)r * 64 + c];
            *(uint4*)(smem + SM_A + r * AP_B + c * 16) = v;
        }
    }

    // per-lane ldmatrix base addresses
    uint32_t aAddr[2];
#pragma unroll
    for (int mf = 0; mf < 2; mf++) {
        int rowA = wm * 32 + mf * 16 + (lane & 15);
        aAddr[mf] = sbase + SM_A + rowA * AP_B + ((lane >> 4) * 8) * 2;
    }
    uint32_t bAddr[2];
#pragma unroll
    for (int n16 = 0; n16 < 2; n16++) {
        int rowB = wn * 32 + n16 * 16 + (lane & 7) + ((lane >> 4) << 3);
        bAddr[n16] = sbase + SM_B + rowB * BP_B + (((lane >> 3) & 1) * 8) * 2;
    }

    // prefetch chunk 0 of tile 0 (128 codes x 128 halves)
    {
        int row = tid >> 2, seg = tid & 3;
        const __nv_bfloat16* src = g_Eh + (size_t)row * D_ + seg * 32;
        uint32_t dst = sbase + SM_B + row * BP_B + seg * 64;
#pragma unroll
        for (int i = 0; i < 4; i++) cp16(dst + i * 16, src + i * 8);
        CP_COMMIT();
    }

    float acc[2][4][4];
#pragma unroll
    for (int mf = 0; mf < 2; mf++)
#pragma unroll
        for (int nf = 0; nf < 4; nf++)
#pragma unroll
            for (int v = 0; v < 4; v++) acc[mf][nf][v] = 0.f;

    float runmin[4]; int runk[4];
#pragma unroll
    for (int s = 0; s < 4; s++) { runmin[s] = FLT_MAX; runk[s] = 0; }

    for (int g = 0; g < GCHUNKS; g++) {
        CP_WAIT0();
        __syncthreads();   // single sync: data g visible AND all warps done with buf (g-1)&1

        if ((g & 3) == 0 && tid < 128)
            esq_s[tid] = g_esq[(g >> 2) * NTILE + tid];

        // prefetch next chunk into the other buffer (safe after the sync above)
        if (g + 1 < GCHUNKS) {
            int gn = g + 1;
            int n0n = (gn >> 2) * NTILE;
            int row = tid >> 2, seg = tid & 3;
            const __nv_bfloat16* src =
                g_Eh + (size_t)(n0n + row) * D_ + (gn & 3) * 128 + seg * 32;
            uint32_t dst = sbase + SM_B + (gn & 1) * BBUF_B + row * BP_B + seg * 64;
#pragma unroll
            for (int i = 0; i < 4; i++) cp16(dst + i * 16, src + i * 8);
            CP_COMMIT();
        }

        // ---- compute 8 k-steps on buffer g&1 ----
        uint32_t kbA = (uint32_t)((g & 3) * 256);      // byte offset in A cols
        uint32_t bb  = (uint32_t)((g & 1) * BBUF_B);
#pragma unroll
        for (int ks = 0; ks < 8; ks++) {
            uint32_t a0[4], a1[4];
            ldsm_x4(a0[0], a0[1], a0[2], a0[3], aAddr[0] + kbA + ks * 32);
            ldsm_x4(a1[0], a1[1], a1[2], a1[3], aAddr[1] + kbA + ks * 32);
            uint32_t bfr[4][2];
#pragma unroll
            for (int n16 = 0; n16 < 2; n16++)
                ldsm_x4(bfr[2 * n16][0], bfr[2 * n16][1],
                        bfr[2 * n16 + 1][0], bfr[2 * n16 + 1][1],
                        bAddr[n16] + bb + ks * 32);
#pragma unroll
            for (int nf = 0; nf < 4; nf++) {
                mma16816(acc[0][nf], a0, bfr[nf]);
                mma16816(acc[1][nf], a1, bfr[nf]);
            }
        }

        // ---- tile epilogue after last chunk of this code tile ----
        if ((g & 3) == 3) {
            int n0 = (g >> 2) * NTILE;
            // stage the 8 esq values this lane needs
            float es[8];
#pragma unroll
            for (int nf = 0; nf < 4; nf++)
#pragma unroll
                for (int p = 0; p < 2; p++)
                    es[nf * 2 + p] = esq_s[wn * 32 + nf * 8 + (lane & 3) * 2 + p];
            // pass 1: per-lane slot minima (slot = mf*2 + rowhalf)
            float sm[4]; int sk[4];
#pragma unroll
            for (int s = 0; s < 4; s++) { sm[s] = FLT_MAX; sk[s] = 0; }
#pragma unroll
            for (int mf = 0; mf < 2; mf++)
#pragma unroll
                for (int nf = 0; nf < 4; nf++)
#pragma unroll
                    for (int v = 0; v < 4; v++) {
                        float dist = fmaf(-2.f, acc[mf][nf][v], es[nf * 2 + (v & 1)]);
                        int slot = mf * 2 + (v >> 1);
                        int k = n0 + wn * 32 + nf * 8 + (lane & 3) * 2 + (v & 1);
                        if (dist < sm[slot]) { sm[slot] = dist; sk[slot] = k; }
                    }
            // quad reduce (lanes sharing a row)
#pragma unroll
            for (int off = 1; off <= 2; off <<= 1) {
#pragma unroll
                for (int s = 0; s < 4; s++) {
                    float od = __shfl_xor_sync(0xffffffffu, sm[s], off);
                    int   ok = __shfl_xor_sync(0xffffffffu, sk[s], off);
                    if (od < sm[s] || (od == sm[s] && ok < sk[s])) { sm[s] = od; sk[s] = ok; }
                }
            }
#pragma unroll
            for (int s = 0; s < 4; s++)
                if (sm[s] < runmin[s]) { runmin[s] = sm[s]; runk[s] = sk[s]; }
            // pass 2: margin appends
#pragma unroll
            for (int mf = 0; mf < 2; mf++)
#pragma unroll
                for (int nf = 0; nf < 4; nf++)
#pragma unroll
                    for (int v = 0; v < 4; v++) {
                        float dist = fmaf(-2.f, acc[mf][nf][v], es[nf * 2 + (v & 1)]);
                        int slot = mf * 2 + (v >> 1);
                        if (dist < runmin[slot] + MARGIN_F) {
                            int row = wm * 32 + mf * 16 + (lane >> 2) + (v >> 1) * 8;
                            int k = n0 + wn * 32 + nf * 8 + (lane & 3) * 2 + (v & 1);
                            int s = atomicAdd(&scnt[row], 1);
                            if (s < CAP)
                                g_cand[tok0 + row][s] = make_float2(dist, __int_as_float(k));
                        }
                        acc[mf][nf][v] = 0.f;   // reset for next tile
                    }
        }
    }

    // ---- final: per-warp row minima -> smem -> global ----
    __syncthreads();
    if ((lane & 3) == 0) {
#pragma unroll
        for (int s = 0; s < 4; s++) {
            int mf = s >> 1, rh = s & 1;
            int row = wm * 32 + mf * 16 + (lane >> 2) + rh * 8;
            wmin[row * 4 + wn] = make_float2(runmin[s], __int_as_float(runk[s]));
        }
    }
    __syncthreads();
    if (tid < 128) {
        float best = FLT_MAX;
#pragma unroll
        for (int w = 0; w < 4; w++) best = fminf(best, wmin[tid * 4 + w].x);
        g_amin[tok0 + tid] = best;
        g_ccnt[tok0 + tid] = scnt[tid];
    }
}

// ============================================================
// K3: exact fp32 rescore of candidates -> g_kidx
// ============================================================
__global__ void __launch_bounds__(128) k_rescore(const float* __restrict__ E) {
    int tok = blockIdx.x * 4 + (threadIdx.x >> 5);
    int lid = threadIdx.x & 31;
    float z[16];
#pragma unroll
    for (int j = 0; j < 16; j++) z[j] = g_Zf[(size_t)tok * D_ + j * 32 + lid];

    int cnt = g_ccnt[tok];
    float amin = g_amin[tok];
    float best = FLT_MAX;
    int bi = 0x7fffffff;

    if (cnt <= CAP) {
        for (int c = 0; c < cnt; c++) {
            float2 cd = g_cand[tok][c];
            if (cd.x > amin + MARGIN_F) continue;      // warp-uniform
            int k = __float_as_int(cd.y);
            float p = 0.f;
            const float* er = E + (size_t)k * D_;
#pragma unroll
            for (int j = 0; j < 16; j++) p += z[j] * er[j * 32 + lid];
#pragma unroll
            for (int o = 16; o > 0; o >>= 1) p += __shfl_down_sync(0xffffffffu, p, o);
            if (lid == 0) {
                float dist = g_esq[k] - 2.0f * p;
                if (dist < best || (dist == best && k < bi)) { best = dist; bi = k; }
            }
        }
    } else {
        // overflow safety net: exact scan of all codes (rare)
        for (int k = 0; k < K_; k++) {
            float p = 0.f;
            const float* er = E + (size_t)k * D_;
#pragma unroll
            for (int j = 0; j < 16; j++) p += z[j] * er[j * 32 + lid];
#pragma unroll
            for (int o = 16; o > 0; o >>= 1) p += __shfl_down_sync(0xffffffffu, p, o);
            if (lid == 0) {
                float dist = g_esq[k] - 2.0f * p;
                if (dist < best) { best = dist; bi = k; }
            }
        }
    }
    if (lid == 0) g_kidx[tok] = bi;
}

// ============================================================
// K4: gather + NCHW output + loss partial
// ============================================================
__global__ void __launch_bounds__(256) k_output(const float* __restrict__ X,
                                                const float* __restrict__ E,
                                                float* __restrict__ out) {
    __shared__ float S[64][65];
    __shared__ int karr[64];
    __shared__ float rbuf[8];
    int t = threadIdx.x;
    int base = blockIdx.x * 64;
    int b = base >> 10, hw0 = base & 1023;
    if (t < 64) karr[t] = g_kidx[base + t];
    __syncthreads();

    float lsum = 0.f;
    size_t blk_base = (size_t)b * D_ * HW_ + hw0;
    for (int dc = 0; dc < D_; dc += 64) {
#pragma unroll
        for (int i = 0; i < 4; i++) {
            int m = (t >> 4) + i * 16;
            int dl = (t & 15) * 4;
            float4 q = *(const float4*)&E[(size_t)karr[m] * D_ + dc + dl];
            S[m][dl] = q.x; S[m][dl + 1] = q.y; S[m][dl + 2] = q.z; S[m][dl + 3] = q.w;
        }
        __syncthreads();
        int hwl = t & 63;
#pragma unroll
        for (int i = 0; i < 16; i++) {
            int dl = (t >> 6) + i * 4;
            size_t addr = blk_base + (size_t)(dc + dl) * HW_ + hwl;
            float z = X[addr];
            float q = S[hwl][dl];
            float df = z - q;
            lsum += df * df;
            out[addr] = q;
        }
        __syncthreads();
    }
#pragma unroll
    for (int o = 16; o > 0; o >>= 1) lsum += __shfl_down_sync(0xffffffffu, lsum, o);
    if ((t & 31) == 0) rbuf[t >> 5] = lsum;
    __syncthreads();
    if (t == 0) {
        float s = 0.f;
#pragma unroll
        for (int w = 0; w < 8; w++) s += rbuf[w];
        atomicAdd(&g_loss, (double)s);
    }
}

__global__ void k_finalize(float* __restrict__ out, int out_size) {
    if (out_size > N_ * D_)
        out[N_ * D_] = (float)(1.25 * g_loss / ((double)N_ * (double)D_));
}

// ============================================================
extern "C" void kernel_launch(void* const* d_in, const int* in_sizes, int n_in,
                              void* d_out, int out_size) {
    const float* X = (const float*)d_in[0];
    const float* E = (const float*)d_in[1];
    if (n_in >= 2 && in_sizes[0] == K_ * D_ && in_sizes[1] == N_ * D_) {
        const float* tmp = X; X = E; E = tmp;
    }
    float* out = (float*)d_out;

    static int smem_set = 0;
    if (!smem_set) {
        cudaFuncSetAttribute(k_gemm, cudaFuncAttributeMaxDynamicSharedMemorySize, SM_TOTAL);
        smem_set = 1;
    }

    k_prep_z<<<dim3(HW_ / 32, D_ / 32, B_), dim3(32, 8)>>>(X);
    k_prep_e<<<K_, 128>>>(E);
    k_gemm<<<N_ / TOK_PER_CTA, 512, SM_TOTAL>>>();
    k_rescore<<<N_ / 4, 128>>>(E);
    k_output<<<N_ / 64, 256>>>(X, E, out);
    k_finalize<<<1, 1>>>(out, out_size);
}

// round 12
// speedup vs baseline: 3.7821x; 1.0029x over previous
#include <cuda_runtime.h>
#include <cuda_bf16.h>
#include <float.h>
#include <stdint.h>

#define B_   32
#define D_   512
#define HW_  1024
#define N_   32768
#define K_   4096

#define TOK_PER_CTA 128
#define NTILE       128                  // codes per tile
#define NUM_TILES   (K_ / NTILE)         // 32
#define GCHUNKS     (NUM_TILES * 4)      // 128 k-chunks of 128 halves
#define CAP         64
#define MARGIN_F    1.5f

// ---- smem layout (bytes) ----
#define AP_B      1040                   // A row pitch: (512+8)*2
#define BP_B      272                    // B row pitch: (128+8)*2
#define BBUF_B    (128 * BP_B)           // 34816 per buffer
#define SM_A      0                      // 128 * 1040 = 133120
#define SM_B      133120                 // 2 * 34816 = 69632
#define SM_ESQ    202752                 // 128 floats
#define SM_SCNT   203264                 // 128 ints
#define SM_WMIN   203776                 // 128 * 4 * float2 = 4096
#define SM_TOTAL  207872

// ---- scratch ----
__device__ __nv_bfloat16 g_Zh[(size_t)N_ * D_];
__device__ float         g_Zf[(size_t)N_ * D_];
__device__ __nv_bfloat16 g_Eh[(size_t)K_ * D_];
__device__ float         g_esq[K_];
__device__ float2        g_cand[N_][CAP];
__device__ int           g_ccnt[N_];
__device__ float         g_amin[N_];
__device__ int           g_kidx[N_];
__device__ double        g_loss;

// ================= helpers =================
__device__ __forceinline__ uint32_t smem_u32(const void* p) {
    uint32_t a;
    asm("{ .reg .u64 t; cvta.to.shared.u64 t, %1; cvt.u32.u64 %0, t; }" : "=r"(a) : "l"(p));
    return a;
}
__device__ __forceinline__ void ldsm_x4(uint32_t& r0, uint32_t& r1, uint32_t& r2, uint32_t& r3,
                                        uint32_t addr) {
    asm volatile("ldmatrix.sync.aligned.m8n8.x4.shared.b16 {%0,%1,%2,%3}, [%4];"
                 : "=r"(r0), "=r"(r1), "=r"(r2), "=r"(r3) : "r"(addr));
}
__device__ __forceinline__ void mma16816(float* d, const uint32_t* a, const uint32_t* b) {
    asm volatile("mma.sync.aligned.m16n8k16.row.col.f32.bf16.bf16.f32 "
                 "{%0,%1,%2,%3}, {%4,%5,%6,%7}, {%8,%9}, {%0,%1,%2,%3};"
                 : "+f"(d[0]), "+f"(d[1]), "+f"(d[2]), "+f"(d[3])
                 : "r"(a[0]), "r"(a[1]), "r"(a[2]), "r"(a[3]), "r"(b[0]), "r"(b[1]));
}
__device__ __forceinline__ void cp16(uint32_t dst, const void* src) {
    asm volatile("cp.async.ca.shared.global [%0], [%1], 16;" :: "r"(dst), "l"(src));
}
#define CP_COMMIT() asm volatile("cp.async.commit_group;" ::: "memory")
#define CP_WAIT0()  asm volatile("cp.async.wait_group 0;" ::: "memory")

// ============================================================
// K0: X[NCHW] -> Zf fp32 + Zh bf16 (token-major)
// ============================================================
__global__ void k_prep_z(const float* __restrict__ X) {
    __shared__ float tile[32][33];
    int b = blockIdx.z, d0 = blockIdx.y * 32, hw0 = blockIdx.x * 32;
    int tx = threadIdx.x, ty = threadIdx.y;       // (32, 8)
#pragma unroll
    for (int i = 0; i < 32; i += 8)
        tile[ty + i][tx] = X[((size_t)b * D_ + d0 + ty + i) * HW_ + hw0 + tx];
    __syncthreads();
#pragma unroll
    for (int i = 0; i < 32; i += 8) {
        size_t idx = (size_t)(b * HW_ + hw0 + ty + i) * D_ + d0 + tx;
        float v = tile[tx][ty + i];
        g_Zf[idx] = v;
        g_Zh[idx] = __float2bfloat16(v);
    }
}

// ============================================================
// K1: E -> Eh bf16 + ||e||^2; zero loss
// ============================================================
__global__ void k_prep_e(const float* __restrict__ E) {
    int row = blockIdx.x, t = threadIdx.x;        // 128 threads
    float s = 0.f;
#pragma unroll
    for (int i = t; i < D_; i += 128) {
        float v = E[(size_t)row * D_ + i];
        g_Eh[(size_t)row * D_ + i] = __float2bfloat16(v);
        s += v * v;
    }
#pragma unroll
    for (int o = 16; o > 0; o >>= 1) s += __shfl_down_sync(0xffffffffu, s, o);
    __shared__ float sb[4];
    if ((t & 31) == 0) sb[t >> 5] = s;
    __syncthreads();
    if (t == 0) {
        g_esq[row] = sb[0] + sb[1] + sb[2] + sb[3];
        if (row == 0) g_loss = 0.0;
    }
}

// ============================================================
// K2: bf16 mma.sync GEMM + margin argmin / candidate collection
//     512 threads, warp grid 4M x 4N, warp tile 32x32,
//     software-pipelined LDSM/HMMA (double-buffered fragments)
// ============================================================
__global__ void __launch_bounds__(512, 1) k_gemm() {
    extern __shared__ char smem[];
    uint32_t sbase = smem_u32(smem);
    int tid = threadIdx.x;
    int lane = tid & 31, wid = tid >> 5;
    int wm = wid >> 2, wn = wid & 3;
    int tok0 = blockIdx.x * TOK_PER_CTA;

    float*  esq_s = (float*)(smem + SM_ESQ);
    int*    scnt  = (int*)(smem + SM_SCNT);
    float2* wmin  = (float2*)(smem + SM_WMIN);

    if (tid < 128) scnt[tid] = 0;

    // ---- load A resident: 128 tokens x 512 bf16, padded rows ----
    {
        const uint4* src = (const uint4*)(g_Zh + (size_t)tok0 * D_);
        for (int i = tid; i < 128 * 64; i += 512) {
            int r = i >> 6, c = i & 63;
            uint4 v = src[(size_t)r * 64 + c];
            *(uint4*)(smem + SM_A + r * AP_B + c * 16) = v;
        }
    }

    // per-lane ldmatrix base addresses
    uint32_t aAddr[2];
#pragma unroll
    for (int mf = 0; mf < 2; mf++) {
        int rowA = wm * 32 + mf * 16 + (lane & 15);
        aAddr[mf] = sbase + SM_A + rowA * AP_B + ((lane >> 4) * 8) * 2;
    }
    uint32_t bAddr[2];
#pragma unroll
    for (int n16 = 0; n16 < 2; n16++) {
        int rowB = wn * 32 + n16 * 16 + (lane & 7) + ((lane >> 4) << 3);
        bAddr[n16] = sbase + SM_B + rowB * BP_B + (((lane >> 3) & 1) * 8) * 2;
    }

    // prefetch chunk 0 of tile 0 (128 codes x 128 halves)
    {
        int row = tid >> 2, seg = tid & 3;
        const __nv_bfloat16* src = g_Eh + (size_t)row * D_ + seg * 32;
        uint32_t dst = sbase + SM_B + row * BP_B + seg * 64;
#pragma unroll
        for (int i = 0; i < 4; i++) cp16(dst + i * 16, src + i * 8);
        CP_COMMIT();
    }

    float acc[2][4][4];
#pragma unroll
    for (int mf = 0; mf < 2; mf++)
#pragma unroll
        for (int nf = 0; nf < 4; nf++)
#pragma unroll
            for (int v = 0; v < 4; v++) acc[mf][nf][v] = 0.f;

    float runmin[4]; int runk[4];
#pragma unroll
    for (int s = 0; s < 4; s++) { runmin[s] = FLT_MAX; runk[s] = 0; }

    for (int g = 0; g < GCHUNKS; g++) {
        CP_WAIT0();
        __syncthreads();   // single sync: data g visible AND all warps done with buf (g-1)&1

        if ((g & 3) == 0 && tid < 128)
            esq_s[tid] = g_esq[(g >> 2) * NTILE + tid];

        // prefetch next chunk into the other buffer (safe after the sync above)
        if (g + 1 < GCHUNKS) {
            int gn = g + 1;
            int n0n = (gn >> 2) * NTILE;
            int row = tid >> 2, seg = tid & 3;
            const __nv_bfloat16* src =
                g_Eh + (size_t)(n0n + row) * D_ + (gn & 3) * 128 + seg * 32;
            uint32_t dst = sbase + SM_B + (gn & 1) * BBUF_B + row * BP_B + seg * 64;
#pragma unroll
            for (int i = 0; i < 4; i++) cp16(dst + i * 16, src + i * 8);
            CP_COMMIT();
        }

        // ---- compute 8 k-steps on buffer g&1, SW-pipelined fragments ----
        uint32_t kbA = (uint32_t)((g & 3) * 256);      // byte offset in A cols
        uint32_t bb  = (uint32_t)((g & 1) * BBUF_B);

        uint32_t af[2][8], bf[2][8];
        // preload ks = 0
        ldsm_x4(af[0][0], af[0][1], af[0][2], af[0][3], aAddr[0] + kbA);
        ldsm_x4(af[0][4], af[0][5], af[0][6], af[0][7], aAddr[1] + kbA);
        ldsm_x4(bf[0][0], bf[0][1], bf[0][2], bf[0][3], bAddr[0] + bb);
        ldsm_x4(bf[0][4], bf[0][5], bf[0][6], bf[0][7], bAddr[1] + bb);
#pragma unroll
        for (int ks = 0; ks < 8; ks++) {
            int cur = ks & 1, nxt = cur ^ 1;
            if (ks < 7) {
                uint32_t ko = (uint32_t)((ks + 1) * 32);
                ldsm_x4(af[nxt][0], af[nxt][1], af[nxt][2], af[nxt][3], aAddr[0] + kbA + ko);
                ldsm_x4(af[nxt][4], af[nxt][5], af[nxt][6], af[nxt][7], aAddr[1] + kbA + ko);
                ldsm_x4(bf[nxt][0], bf[nxt][1], bf[nxt][2], bf[nxt][3], bAddr[0] + bb + ko);
                ldsm_x4(bf[nxt][4], bf[nxt][5], bf[nxt][6], bf[nxt][7], bAddr[1] + bb + ko);
            }
#pragma unroll
            for (int nf = 0; nf < 4; nf++) {
                mma16816(acc[0][nf], &af[cur][0], &bf[cur][nf * 2]);
                mma16816(acc[1][nf], &af[cur][4], &bf[cur][nf * 2]);
            }
        }

        // ---- tile epilogue after last chunk of this code tile ----
        if ((g & 3) == 3) {
            int n0 = (g >> 2) * NTILE;
            // stage the 8 esq values this lane needs
            float es[8];
#pragma unroll
            for (int nf = 0; nf < 4; nf++)
#pragma unroll
                for (int p = 0; p < 2; p++)
                    es[nf * 2 + p] = esq_s[wn * 32 + nf * 8 + (lane & 3) * 2 + p];
            // pass 1: per-lane slot minima (slot = mf*2 + rowhalf)
            float sm[4]; int sk[4];
#pragma unroll
            for (int s = 0; s < 4; s++) { sm[s] = FLT_MAX; sk[s] = 0; }
#pragma unroll
            for (int mf = 0; mf < 2; mf++)
#pragma unroll
                for (int nf = 0; nf < 4; nf++)
#pragma unroll
                    for (int v = 0; v < 4; v++) {
                        float dist = fmaf(-2.f, acc[mf][nf][v], es[nf * 2 + (v & 1)]);
                        int slot = mf * 2 + (v >> 1);
                        int k = n0 + wn * 32 + nf * 8 + (lane & 3) * 2 + (v & 1);
                        if (dist < sm[slot]) { sm[slot] = dist; sk[slot] = k; }
                    }
            // quad reduce (lanes sharing a row)
#pragma unroll
            for (int off = 1; off <= 2; off <<= 1) {
#pragma unroll
                for (int s = 0; s < 4; s++) {
                    float od = __shfl_xor_sync(0xffffffffu, sm[s], off);
                    int   ok = __shfl_xor_sync(0xffffffffu, sk[s], off);
                    if (od < sm[s] || (od == sm[s] && ok < sk[s])) { sm[s] = od; sk[s] = ok; }
                }
            }
#pragma unroll
            for (int s = 0; s < 4; s++)
                if (sm[s] < runmin[s]) { runmin[s] = sm[s]; runk[s] = sk[s]; }
            // pass 2: margin appends
#pragma unroll
            for (int mf = 0; mf < 2; mf++)
#pragma unroll
                for (int nf = 0; nf < 4; nf++)
#pragma unroll
                    for (int v = 0; v < 4; v++) {
                        float dist = fmaf(-2.f, acc[mf][nf][v], es[nf * 2 + (v & 1)]);
                        int slot = mf * 2 + (v >> 1);
                        if (dist < runmin[slot] + MARGIN_F) {
                            int row = wm * 32 + mf * 16 + (lane >> 2) + (v >> 1) * 8;
                            int k = n0 + wn * 32 + nf * 8 + (lane & 3) * 2 + (v & 1);
                            int s = atomicAdd(&scnt[row], 1);
                            if (s < CAP)
                                g_cand[tok0 + row][s] = make_float2(dist, __int_as_float(k));
                        }
                        acc[mf][nf][v] = 0.f;   // reset for next tile
                    }
        }
    }

    // ---- final: per-warp row minima -> smem -> global ----
    __syncthreads();
    if ((lane & 3) == 0) {
#pragma unroll
        for (int s = 0; s < 4; s++) {
            int mf = s >> 1, rh = s & 1;
            int row = wm * 32 + mf * 16 + (lane >> 2) + rh * 8;
            wmin[row * 4 + wn] = make_float2(runmin[s], __int_as_float(runk[s]));
        }
    }
    __syncthreads();
    if (tid < 128) {
        float best = FLT_MAX;
#pragma unroll
        for (int w = 0; w < 4; w++) best = fminf(best, wmin[tid * 4 + w].x);
        g_amin[tok0 + tid] = best;
        g_ccnt[tok0 + tid] = scnt[tid];
    }
}

// ============================================================
// K3: exact fp32 rescore of candidates -> g_kidx
// ============================================================
__global__ void __launch_bounds__(128) k_rescore(const float* __restrict__ E) {
    int tok = blockIdx.x * 4 + (threadIdx.x >> 5);
    int lid = threadIdx.x & 31;
    float z[16];
#pragma unroll
    for (int j = 0; j < 16; j++) z[j] = g_Zf[(size_t)tok * D_ + j * 32 + lid];

    int cnt = g_ccnt[tok];
    float amin = g_amin[tok];
    float best = FLT_MAX;
    int bi = 0x7fffffff;

    if (cnt <= CAP) {
        for (int c = 0; c < cnt; c++) {
            float2 cd = g_cand[tok][c];
            if (cd.x > amin + MARGIN_F) continue;      // warp-uniform
            int k = __float_as_int(cd.y);
            float p = 0.f;
            const float* er = E + (size_t)k * D_;
#pragma unroll
            for (int j = 0; j < 16; j++) p += z[j] * er[j * 32 + lid];
#pragma unroll
            for (int o = 16; o > 0; o >>= 1) p += __shfl_down_sync(0xffffffffu, p, o);
            if (lid == 0) {
                float dist = g_esq[k] - 2.0f * p;
                if (dist < best || (dist == best && k < bi)) { best = dist; bi = k; }
            }
        }
    } else {
        // overflow safety net: exact scan of all codes (rare)
        for (int k = 0; k < K_; k++) {
            float p = 0.f;
            const float* er = E + (size_t)k * D_;
#pragma unroll
            for (int j = 0; j < 16; j++) p += z[j] * er[j * 32 + lid];
#pragma unroll
            for (int o = 16; o > 0; o >>= 1) p += __shfl_down_sync(0xffffffffu, p, o);
            if (lid == 0) {
                float dist = g_esq[k] - 2.0f * p;
                if (dist < best) { best = dist; bi = k; }
            }
        }
    }
    if (lid == 0) g_kidx[tok] = bi;
}

// ============================================================
// K4: gather + NCHW output + loss partial
// ============================================================
__global__ void __launch_bounds__(256) k_output(const float* __restrict__ X,
                                                const float* __restrict__ E,
                                                float* __restrict__ out) {
    __shared__ float S[64][65];
    __shared__ int karr[64];
    __shared__ float rbuf[8];
    int t = threadIdx.x;
    int base = blockIdx.x * 64;
    int b = base >> 10, hw0 = base & 1023;
    if (t < 64) karr[t] = g_kidx[base + t];
    __syncthreads();

    float lsum = 0.f;
    size_t blk_base = (size_t)b * D_ * HW_ + hw0;
    for (int dc = 0; dc < D_; dc += 64) {
#pragma unroll
        for (int i = 0; i < 4; i++) {
            int m = (t >> 4) + i * 16;
            int dl = (t & 15) * 4;
            float4 q = *(const float4*)&E[(size_t)karr[m] * D_ + dc + dl];
            S[m][dl] = q.x; S[m][dl + 1] = q.y; S[m][dl + 2] = q.z; S[m][dl + 3] = q.w;
        }
        __syncthreads();
        int hwl = t & 63;
#pragma unroll
        for (int i = 0; i < 16; i++) {
            int dl = (t >> 6) + i * 4;
            size_t addr = blk_base + (size_t)(dc + dl) * HW_ + hwl;
            float z = X[addr];
            float q = S[hwl][dl];
            float df = z - q;
            lsum += df * df;
            out[addr] = q;
        }
        __syncthreads();
    }
#pragma unroll
    for (int o = 16; o > 0; o >>= 1) lsum += __shfl_down_sync(0xffffffffu, lsum, o);
    if ((t & 31) == 0) rbuf[t >> 5] = lsum;
    __syncthreads();
    if (t == 0) {
        float s = 0.f;
#pragma unroll
        for (int w = 0; w < 8; w++) s += rbuf[w];
        atomicAdd(&g_loss, (double)s);
    }
}

__global__ void k_finalize(float* __restrict__ out, int out_size) {
    if (out_size > N_ * D_)
        out[N_ * D_] = (float)(1.25 * g_loss / ((double)N_ * (double)D_));
}

// ============================================================
extern "C" void kernel_launch(void* const* d_in, const int* in_sizes, int n_in,
                              void* d_out, int out_size) {
    const float* X = (const float*)d_in[0];
    const float* E = (const float*)d_in[1];
    if (n_in >= 2 && in_sizes[0] == K_ * D_ && in_sizes[1] == N_ * D_) {
        const float* tmp = X; X = E; E = tmp;
    }
    float* out = (float*)d_out;

    static int smem_set = 0;
    if (!smem_set) {
        cudaFuncSetAttribute(k_gemm, cudaFuncAttributeMaxDynamicSharedMemorySize, SM_TOTAL);
        smem_set = 1;
    }

    k_prep_z<<<dim3(HW_ / 32, D_ / 32, B_), dim3(32, 8)>>>(X);
    k_prep_e<<<K_, 128>>>(E);
    k_gemm<<<N_ / TOK_PER_CTA, 512, SM_TOTAL>>>();
    k_rescore<<<N_ / 4, 128>>>(E);
    k_output<<<N_ / 64, 256>>>(X, E, out);
    k_finalize<<<1, 1>>>(out, out_size);
}